// round 16
// baseline (speedup 1.0000x reference)
#include <cuda_runtime.h>

#define B_TOTAL 32768
#define T_LEN   200

// Scratch (allocation-free rule: __device__ globals)
__device__ float g_Hh[2 * 800 * B_TOTAL];   // [r][k=4t+u][b]   210 MB
__device__ float g_so[2 * B_TOTAL];         // folded-'other' partial dots

struct Params {
    const float* p[29];
    float* out;
};

// ---- fast activations (hot loop): MUFU.TANH — validated rel_err 2.2e-7 ----
__device__ __forceinline__ float tanha(float x) {
    float r; asm("tanh.approx.f32 %0, %1;" : "=f"(r) : "f"(x)); return r;
}
__device__ __forceinline__ float siga(float x) {
    return fmaf(tanha(0.5f * x), 0.5f, 0.5f);
}
// ---- accurate activations (epilogue/tail only) ----
__device__ __forceinline__ float sigacc(float x) {
    return __fdividef(1.0f, 1.0f + __expf(-x));
}
__device__ __forceinline__ float tanhacc(float x) {
    float e = __expf(-2.0f * x);
    return __fdividef(2.0f, 1.0f + e) - 1.0f;
}

// ---- tf32 split: x -> hi (tf32) + lo (tf32 of residual) ----
__device__ __forceinline__ void tf32split(float x, float& hf, float& lf) {
    unsigned hb, lb;
    asm("cvt.rna.tf32.f32 %0, %1;" : "=r"(hb) : "f"(x));
    float h = __uint_as_float(hb);
    asm("cvt.rna.tf32.f32 %0, %1;" : "=r"(lb) : "f"(x - h));
    hf = h; lf = __uint_as_float(lb);
}

#define MMA_TF32(c, a0, a1, a2, a3, b0, b1)                                   \
    asm volatile("mma.sync.aligned.m16n8k8.row.col.f32.tf32.tf32.f32 "        \
                 "{%0,%1,%2,%3}, {%4,%5,%6,%7}, {%8,%9}, {%0,%1,%2,%3};"      \
                 : "+f"((c)[0]), "+f"((c)[1]), "+f"((c)[2]), "+f"((c)[3])     \
                 : "r"(a0), "r"(a1), "r"(a2), "r"(a3), "r"(b0), "r"(b1))

// ---------------------------------------------------------------------------
// k_lstm: scalar fp32 gate math (arithmetically identical to the measured
// packed version — FFMA2 = 2 independent FMAs — minus all pack/unpack MOVs).
// float4 LDS keeps shared-load count at 60 LDS.128/step.
// ---------------------------------------------------------------------------
__global__ void __launch_bounds__(128, 4) k_lstm(Params P) {
    __shared__ float sml[256];
    __shared__ float wef[200];

    const int tid = threadIdx.x;
    const int r   = blockIdx.y;
    const int b   = blockIdx.x * 128 + tid;

    const float* __restrict__ Wih0 = P.p[1 + 8 * r];
    const float* __restrict__ Whh0 = P.p[2 + 8 * r];
    const float* __restrict__ bih0 = P.p[3 + 8 * r];
    const float* __restrict__ bhh0 = P.p[4 + 8 * r];
    const float* __restrict__ Wih1 = P.p[5 + 8 * r];
    const float* __restrict__ Whh1 = P.p[6 + 8 * r];
    const float* __restrict__ bih1 = P.p[7 + 8 * r];
    const float* __restrict__ bhh1 = P.p[8 + 8 * r];

    // sml[0:16) Wih0   [16:32) bih0+bhh0   [32:48) bih1+bhh1
    // [48:112) Whh0 packed [j][16] (pos j*16+k = W[k][j])
    // [112:176) Wih1 packed   [176:240) Whh1 packed
    if (tid < 16) {
        sml[tid]      = Wih0[tid];
        sml[16 + tid] = bih0[tid] + bhh0[tid];
        sml[32 + tid] = bih1[tid] + bhh1[tid];
    }
    if (tid < 64) {
        int j = tid >> 4, k = tid & 15;
        sml[48  + tid] = Whh0[k * 4 + j];
        sml[112 + tid] = Wih1[k * 4 + j];
        sml[176 + tid] = Whh1[k * 4 + j];
    }
    {
        const float* __restrict__ Wp  = P.p[17];
        const float* __restrict__ W3b = P.p[27] + 40;
        for (int t = tid; t < 200; t += 128) {
            float s = 0.f;
            #pragma unroll 8
            for (int v = 0; v < 40; ++v) s = fmaf(W3b[v], Wp[v * 400 + r * 200 + t], s);
            wef[t] = s;
        }
    }
    __syncthreads();

    const float* __restrict__ xrow = P.p[0] + (size_t)b * 400 + r * 200;
    float* __restrict__ hB = g_Hh + (size_t)r * 800 * B_TOTAL + b;

    float c0v[4] = {0.f, 0.f, 0.f, 0.f};
    float c1v[4] = {0.f, 0.f, 0.f, 0.f};
    float h0[4]  = {0.f, 0.f, 0.f, 0.f};
    float h1[4]  = {0.f, 0.f, 0.f, 0.f};
    float so = 0.f;
    size_t hoff = 0;

    #pragma unroll 1
    for (int t4 = 0; t4 < 50; ++t4) {
        float4 xq = *(const float4*)(xrow + t4 * 4);
        float xs[4] = {xq.x, xq.y, xq.z, xq.w};
        #pragma unroll
        for (int s = 0; s < 4; ++s) {
            const int t = t4 * 4 + s;
            const float xv = xs[s];
            so = fmaf(wef[t], xv, so);

            float g[16];
            // layer 0: g = x*Wih0 + b0 + Whh0 @ h0  (float4 LDS, scalar FMA)
            {
                const float4* wx = (const float4*)(sml);
                const float4* bb = (const float4*)(sml + 16);
                #pragma unroll
                for (int q = 0; q < 4; ++q) {
                    float4 w = wx[q], bv = bb[q];
                    g[4 * q + 0] = fmaf(xv, w.x, bv.x);
                    g[4 * q + 1] = fmaf(xv, w.y, bv.y);
                    g[4 * q + 2] = fmaf(xv, w.z, bv.z);
                    g[4 * q + 3] = fmaf(xv, w.w, bv.w);
                }
                #pragma unroll
                for (int j = 0; j < 4; ++j) {
                    const float4* wr = (const float4*)(sml + 48 + j * 16);
                    const float hj = h0[j];
                    #pragma unroll
                    for (int q = 0; q < 4; ++q) {
                        float4 w = wr[q];
                        g[4 * q + 0] = fmaf(w.x, hj, g[4 * q + 0]);
                        g[4 * q + 1] = fmaf(w.y, hj, g[4 * q + 1]);
                        g[4 * q + 2] = fmaf(w.z, hj, g[4 * q + 2]);
                        g[4 * q + 3] = fmaf(w.w, hj, g[4 * q + 3]);
                    }
                }
            }
            #pragma unroll
            for (int u = 0; u < 4; ++u) {
                float ig = siga(g[u]);
                float fg = siga(g[u + 4]);
                float gg = tanha(g[u + 8]);
                float og = siga(g[u + 12]);
                c0v[u] = fmaf(fg, c0v[u], ig * gg);
                h0[u]  = og * tanha(c0v[u]);
            }
            // layer 1: g = b1s + Wih1 @ h0_new + Whh1 @ h1
            {
                const float4* bb = (const float4*)(sml + 32);
                #pragma unroll
                for (int q = 0; q < 4; ++q) {
                    float4 bv = bb[q];
                    g[4 * q + 0] = bv.x; g[4 * q + 1] = bv.y;
                    g[4 * q + 2] = bv.z; g[4 * q + 3] = bv.w;
                }
                #pragma unroll
                for (int j = 0; j < 4; ++j) {
                    const float4* wa = (const float4*)(sml + 112 + j * 16);
                    const float4* wb = (const float4*)(sml + 176 + j * 16);
                    const float haj = h0[j], hbj = h1[j];
                    #pragma unroll
                    for (int q = 0; q < 4; ++q) {
                        float4 a = wa[q], w = wb[q];
                        g[4 * q + 0] = fmaf(a.x, haj, g[4 * q + 0]);
                        g[4 * q + 1] = fmaf(a.y, haj, g[4 * q + 1]);
                        g[4 * q + 2] = fmaf(a.z, haj, g[4 * q + 2]);
                        g[4 * q + 3] = fmaf(a.w, haj, g[4 * q + 3]);
                        g[4 * q + 0] = fmaf(w.x, hbj, g[4 * q + 0]);
                        g[4 * q + 1] = fmaf(w.y, hbj, g[4 * q + 1]);
                        g[4 * q + 2] = fmaf(w.z, hbj, g[4 * q + 2]);
                        g[4 * q + 3] = fmaf(w.w, hbj, g[4 * q + 3]);
                    }
                }
            }
            #pragma unroll
            for (int u = 0; u < 4; ++u) {
                float ig = siga(g[u]);
                float fg = siga(g[u + 4]);
                float gg = tanha(g[u + 8]);
                float og = siga(g[u + 12]);
                c1v[u] = fmaf(fg, c1v[u], ig * gg);
                float h = og * tanha(c1v[u]);
                h1[u] = h;
                hB[hoff + (size_t)u * B_TOTAL] = h;   // coalesced across warp
            }
            hoff += 4 * B_TOTAL;
        }
    }
    g_so[r * B_TOTAL + b] = so;
}

// ---------------------------------------------------------------------------
// k_gemm v2: tf32 tensor-core GEMM (3-pass hi/lo split ~ fp32 accuracy).
// Block: 64 batch rows x 256 cols (both halves). 8 warps, each m16 x n64.
// B staged directly from WH/WL [n][k] (mma "col" layout) — no pre-transpose.
// Then fused W1/W2/W3 tail + sigmoid (unchanged, proven).
// ---------------------------------------------------------------------------
#define ZC_STRIDE 268
#define ZC_FL     (64 * ZC_STRIDE)          // 17152
#define ST_FL     13824                     // sAh/sAl(2*2304) + sBh/sBl(2*4608)
#define SAH_OFF   0
#define SAL_OFF   2304
#define SBH_OFF   4608
#define SBL_OFF   9216
#define Z1_STRIDE 84
#define Z1_FL     (64 * Z1_STRIDE)          // 5376
#define Z2_STRIDE 44
#define Z2_FL     (64 * Z2_STRIDE)          // 2816
#define SW1_STRIDE 260
#define SW2_STRIDE 84
#define GEMM_SMEM_FL (ZC_FL + ST_FL + Z1_FL + Z2_FL + 416)   // 39584 fl = 158.3KB

__global__ void __launch_bounds__(256, 1) k_gemm(Params P) {
    extern __shared__ float smem[];
    float* zc  = smem;                       // [64][268]
    float* r1  = smem + ZC_FL;               // staging / sW1 / sW2
    float* z1s = r1 + ST_FL;                 // [64][84]
    float* z2s = z1s + Z1_FL;                // [64][44]
    float* sbias = z2s + Z2_FL;              // [256] bH|bL
    float* sb1 = sbias + 256;                // [80]
    float* sb2 = sb1 + 80;                   // [40]
    float* sw3 = sb2 + 40;                   // [40]

    const int tid  = threadIdx.x;
    const int m0   = blockIdx.x * 64;
    const int lane = tid & 31;
    const int w    = tid >> 5;
    const int mb   = (w >> 1) << 4;          // warp m-base: 0/16/32/48
    const int nbase = (w & 1) << 6;          // warp n-base: 0/64
    const int lg   = lane >> 2;              // groupID
    const int lt   = lane & 3;               // threadID_in_group

    if (tid < 128) {
        sbias[tid]       = P.p[20][tid];     // bH
        sbias[128 + tid] = P.p[22][tid];     // bL
    }
    if (tid < 80) sb1[tid] = P.p[24][tid];
    if (tid < 40) { sb2[tid] = P.p[26][tid]; sw3[tid] = P.p[27][tid]; }

    float* sAh = r1 + SAH_OFF;               // [64 rows][36 k]
    float* sAl = r1 + SAL_OFF;
    float* sBh = r1 + SBH_OFF;               // [128 n][36 k]
    float* sBl = r1 + SBL_OFF;

    #pragma unroll 1
    for (int half = 0; half < 2; ++half) {
        const float* __restrict__ Hh = g_Hh + (size_t)half * 800 * B_TOTAL;  // [800][B]
        const float* __restrict__ Wsrc = P.p[19 + 2 * half];                 // [128][800]

        float acc[8][4];
        #pragma unroll
        for (int nt = 0; nt < 8; ++nt)
            #pragma unroll
            for (int q = 0; q < 4; ++q) acc[nt][q] = 0.f;

        #pragma unroll 1
        for (int k0 = 0; k0 < 800; k0 += 32) {
            __syncthreads();
            // stage A: g_Hh[k][b] -> sAh/sAl[row][k]  (coalesced 256B LDG runs)
            #pragma unroll
            for (int it = 0; it < 2; ++it) {
                int idx = tid + it * 256;            // 0..511
                int k = idx >> 4, rq = idx & 15;
                float4 v = *(const float4*)(Hh + (size_t)(k0 + k) * B_TOTAL + m0 + rq * 4);
                float h0f, l0f, h1f, l1f, h2f, l2f, h3f, l3f;
                tf32split(v.x, h0f, l0f); tf32split(v.y, h1f, l1f);
                tf32split(v.z, h2f, l2f); tf32split(v.w, h3f, l3f);
                int base = (rq * 4) * 36 + k;
                sAh[base]          = h0f; sAl[base]          = l0f;
                sAh[base + 36]     = h1f; sAl[base + 36]     = l1f;
                sAh[base + 72]     = h2f; sAl[base + 72]     = l2f;
                sAh[base + 108]    = h3f; sAl[base + 108]    = l3f;
            }
            // stage B: W[n][k] -> sBh/sBl[n][k]  (coalesced 128B LDG runs)
            #pragma unroll
            for (int it = 0; it < 4; ++it) {
                int idx = tid + it * 256;            // 0..1023
                int n = idx >> 3, kq = idx & 7;
                float4 v = *(const float4*)(Wsrc + n * 800 + k0 + kq * 4);
                float h0f, l0f, h1f, l1f, h2f, l2f, h3f, l3f;
                tf32split(v.x, h0f, l0f); tf32split(v.y, h1f, l1f);
                tf32split(v.z, h2f, l2f); tf32split(v.w, h3f, l3f);
                int base = n * 36 + kq * 4;
                sBh[base]     = h0f; sBl[base]     = l0f;
                sBh[base + 1] = h1f; sBl[base + 1] = l1f;
                sBh[base + 2] = h2f; sBl[base + 2] = l2f;
                sBh[base + 3] = h3f; sBl[base + 3] = l3f;
            }
            __syncthreads();

            #pragma unroll
            for (int kk = 0; kk < 32; kk += 8) {
                // A fragments (m16k8, row-major): a0:(lg,lt) a1:(lg+8,lt) a2:(lg,lt+4) a3:(lg+8,lt+4)
                int ar = (mb + lg) * 36 + kk + lt;
                unsigned ah0 = __float_as_uint(sAh[ar]);
                unsigned ah1 = __float_as_uint(sAh[ar + 8 * 36]);
                unsigned ah2 = __float_as_uint(sAh[ar + 4]);
                unsigned ah3 = __float_as_uint(sAh[ar + 8 * 36 + 4]);
                unsigned al0 = __float_as_uint(sAl[ar]);
                unsigned al1 = __float_as_uint(sAl[ar + 8 * 36]);
                unsigned al2 = __float_as_uint(sAl[ar + 4]);
                unsigned al3 = __float_as_uint(sAl[ar + 8 * 36 + 4]);
                #pragma unroll
                for (int nt = 0; nt < 8; ++nt) {
                    // B fragments (k8n8, col-major): b0:(k=lt, n=lg) b1:(k=lt+4, n=lg)
                    int br = (nbase + nt * 8 + lg) * 36 + kk + lt;
                    unsigned bh0 = __float_as_uint(sBh[br]);
                    unsigned bh1 = __float_as_uint(sBh[br + 4]);
                    unsigned bl0 = __float_as_uint(sBl[br]);
                    unsigned bl1 = __float_as_uint(sBl[br + 4]);
                    MMA_TF32(acc[nt], ah0, ah1, ah2, ah3, bh0, bh1);
                    MMA_TF32(acc[nt], al0, al1, al2, al3, bh0, bh1);
                    MMA_TF32(acc[nt], ah0, ah1, ah2, ah3, bl0, bl1);
                }
            }
        }

        // epilogue: zc[row][half*128+col] = tanh(acc + bias)
        // C layout: c0:(lg, 2lt) c1:(lg, 2lt+1) c2:(lg+8, 2lt) c3:(lg+8, 2lt+1)
        const int off = half * 128;
        #pragma unroll
        for (int nt = 0; nt < 8; ++nt) {
            int col = nbase + nt * 8 + 2 * lt;
            int row = mb + lg;
            zc[row * ZC_STRIDE + off + col]           = tanhacc(acc[nt][0] + sbias[off + col]);
            zc[row * ZC_STRIDE + off + col + 1]       = tanhacc(acc[nt][1] + sbias[off + col + 1]);
            zc[(row + 8) * ZC_STRIDE + off + col]     = tanhacc(acc[nt][2] + sbias[off + col]);
            zc[(row + 8) * ZC_STRIDE + off + col + 1] = tanhacc(acc[nt][3] + sbias[off + col + 1]);
        }
        __syncthreads();
    }

    // ---- tail (unchanged, proven) ----
    const int row = tid >> 2;        // 0..63
    const int cch = tid & 3;         // 0..3
    const float* __restrict__ W1 = P.p[23];
    const float* __restrict__ W2 = P.p[25];

    #pragma unroll 1
    for (int pass = 0; pass < 2; ++pass) {
        __syncthreads();
        for (int idx = tid; idx < 40 * 64; idx += 256) {
            int q = idx & 63, uu = idx >> 6;
            *(float4*)(r1 + uu * SW1_STRIDE + q * 4) =
                *(const float4*)(W1 + (pass * 40 + uu) * 256 + q * 4);
        }
        __syncthreads();
        const float* zr = zc + row * ZC_STRIDE;
        #pragma unroll 1
        for (int i = 0; i < 10; ++i) {
            int ul = cch * 10 + i;
            const float* w1 = r1 + ul * SW1_STRIDE;
            float s0 = 0.f, s1 = 0.f, s2 = 0.f, s3 = 0.f;
            #pragma unroll
            for (int q = 0; q < 256; q += 4) {
                s0 = fmaf(w1[q],     zr[q],     s0);
                s1 = fmaf(w1[q + 1], zr[q + 1], s1);
                s2 = fmaf(w1[q + 2], zr[q + 2], s2);
                s3 = fmaf(w1[q + 3], zr[q + 3], s3);
            }
            int u = pass * 40 + ul;
            float s = sb1[u] + (s0 + s1) + (s2 + s3);
            z1s[row * Z1_STRIDE + u] = tanhacc(s);
        }
    }

    __syncthreads();
    for (int idx = tid; idx < 3200; idx += 256) {
        int v = idx / 80, kk = idx - v * 80;
        r1[v * SW2_STRIDE + kk] = W2[idx];
    }
    __syncthreads();
    {
        const float* zr = z1s + row * Z1_STRIDE;
        #pragma unroll 1
        for (int i = 0; i < 10; ++i) {
            int v = cch * 10 + i;
            const float* w2 = r1 + v * SW2_STRIDE;
            float s0 = 0.f, s1 = 0.f;
            #pragma unroll
            for (int q = 0; q < 80; q += 2) {
                s0 = fmaf(w2[q],     zr[q],     s0);
                s1 = fmaf(w2[q + 1], zr[q + 1], s1);
            }
            float s = sb2[v] + s0 + s1;
            z2s[row * Z2_STRIDE + v] = tanhacc(s);
        }
    }

    __syncthreads();
    if (tid < 64) {
        int gb = m0 + tid;
        const float* __restrict__ bp  = P.p[18];
        const float* __restrict__ W3b = P.p[27] + 40;
        float be = P.p[28][0];
        #pragma unroll 8
        for (int v = 0; v < 40; ++v) be = fmaf(W3b[v], bp[v], be);
        float r3 = be + g_so[gb] + g_so[B_TOTAL + gb];
        const float* z2r = z2s + tid * Z2_STRIDE;
        #pragma unroll
        for (int v = 0; v < 40; ++v) r3 = fmaf(sw3[v], z2r[v], r3);
        P.out[gb] = sigacc(r3);
    }
}

extern "C" void kernel_launch(void* const* d_in, const int* in_sizes, int n_in,
                              void* d_out, int out_size) {
    (void)in_sizes; (void)n_in; (void)out_size;
    Params P;
    for (int i = 0; i < 29; ++i) P.p[i] = (const float*)d_in[i];
    P.out = (float*)d_out;

    const size_t gsh = (size_t)GEMM_SMEM_FL * sizeof(float);   // ~158.3 KB
    cudaFuncSetAttribute(k_gemm, cudaFuncAttributeMaxDynamicSharedMemorySize, (int)gsh);

    k_lstm<<<dim3(256, 2), 128>>>(P);
    k_gemm<<<512, 256, gsh>>>(P);
}